// round 14
// baseline (speedup 1.0000x reference)
#include <cuda_runtime.h>
#include <cuda_fp16.h>
#include <cstdint>

#define NPIX 65536
#define DDIM 256
#define KCODES 512
#define MT 64
#define THREADS 512
#define ZS 268                 // z_s row stride (floats)
#define Z_OFF 0
#define B_OFF 17152            // 2 x 2048-float cp.async buffers (8KB each)
#define ZSQ_OFF 21248
#define ESQ_OFF 21312
#define SMEM_FLOATS 21824      // 87,296 bytes -> 2 CTAs/SM
#define EPS 2e-4f              // rescue window (fp16 filter dist err ~1.4e-5 rms)

__device__ float g_esq[KCODES];
// B fragments (fp16): [tt(32)][ks(4)][nt8(8)][lane(32)][b0,b1]  (f16x2 words)
__device__ __align__(16) float e_frag[32 * 2048];

static __device__ __forceinline__ uint32_t smem_u32(const void* p) {
    uint32_t a;
    asm("{ .reg .u64 t; cvta.to.shared.u64 t, %1; cvt.u32.u64 %0, t; }" : "=r"(a) : "l"(p));
    return a;
}
// pack two f32 -> f16x2; first operand lands in UPPER 16 bits
static __device__ __forceinline__ uint32_t f16pack(float hi, float lo) {
    uint32_t r;
    asm("cvt.rn.f16x2.f32 %0, %1, %2;" : "=r"(r) : "f"(hi), "f"(lo));
    return r;
}
static __device__ __forceinline__ void mma_fp16(float* c, const uint32_t* a,
                                                uint32_t b0, uint32_t b1) {
    asm volatile("mma.sync.aligned.m16n8k16.row.col.f32.f16.f16.f32 "
                 "{%0,%1,%2,%3}, {%4,%5,%6,%7}, {%8,%9}, {%0,%1,%2,%3};"
                 : "+f"(c[0]), "+f"(c[1]), "+f"(c[2]), "+f"(c[3])
                 : "r"(a[0]), "r"(a[1]), "r"(a[2]), "r"(a[3]), "r"(b0), "r"(b1));
}
#define CP_ASYNC16(saddr, gptr) \
    asm volatile("cp.async.ca.shared.global [%0], [%1], 16;" :: "r"(saddr), "l"(gptr))
#define CP_COMMIT()  asm volatile("cp.async.commit_group;" ::: "memory")
#define CP_WAIT0()   asm volatile("cp.async.wait_group 0;" ::: "memory")

// ---- prep: scatter codebook into fp16 B-fragment image + esq (exact reference order) ----
__global__ void prep_kernel(const float* __restrict__ cb) {
    __shared__ float part[4];
    const int n = blockIdx.x;
    const int t = threadIdx.x;
    const int d = t * 2;
    const int g = n & 7, nt8 = (n >> 3) & 7, nch = n >> 6;

    float v0 = cb[n * DDIM + d];
    float v1 = cb[n * DDIM + d + 1];
    uint32_t pk = f16pack(v1, v0);          // lower 16 = k-even
    int tt   = nch * 4 + (d >> 6);
    int ks   = (d >> 4) & 3;
    int ko   = d & 15;
    int half = ko >> 3;
    int tig  = (ko >> 1) & 3;
    int lane = g * 4 + tig;
    e_frag[tt * 2048 + ((ks * 8 + nt8) * 32 + lane) * 2 + half] = __uint_as_float(pk);

    if (t < 4) {
        float s = 0.f;
        for (int i = 0; i < DDIM / 4; i++) {
            float x = cb[n * DDIM + i * 4 + t];
            s = __fadd_rn(s, __fmul_rn(x, x));
        }
        part[t] = s;
    }
    __syncthreads();
    if (t == 0)
        g_esq[n] = __fadd_rn(__fadd_rn(part[0], part[1]), __fadd_rn(part[2], part[3]));
}

__global__ __launch_bounds__(THREADS, 2)
void vq_mma_kernel(const float* __restrict__ z, const float* __restrict__ cb,
                   float* __restrict__ out) {
    extern __shared__ __align__(16) float smem[];
    float* z_s   = smem + Z_OFF;
    float* bbuf  = smem + B_OFF;
    float* zsq_s = smem + ZSQ_OFF;
    float* esq_s = smem + ESQ_OFF;
    const uint32_t bbuf_s = smem_u32(bbuf);

    const int tid  = threadIdx.x;
    const int warp = tid >> 5;
    const int lane = tid & 31;
    const int g    = lane >> 2;      // 0..7
    const int tig  = lane & 3;       // 0..3
    const int wm   = warp & 3;       // M-warp 0..3 -> mtile wm (16 px)
    const int wn   = warp >> 2;      // N-warp 0..3 -> nt8 {wn*2, wn*2+1}

    const int pix_base = blockIdx.x * MT;
    const float* zbase = z + (size_t)(pix_base >> 10) * (DDIM * 1024) + (pix_base & 1023);

    // ---- transpose z: gmem [d][px] -> z_s[px][d] via staged buffer (stride 68) ----
    float* stage = bbuf;   // 32*68 = 2176 floats <= 4096
    for (int db = 0; db < 8; db++) {
        const int dblk = db * 32;
        __syncthreads();
        {
            int d  = tid >> 4;                    // 0..31
            int p4 = (tid & 15) << 2;             // 0..60
            float4 v = *(const float4*)(zbase + (size_t)(dblk + d) * 1024 + p4);
            *(float4*)(stage + d * 68 + p4) = v;
        }
        __syncthreads();
        {
            int p   = tid & 63;                   // 0..63
            int dl4 = (tid >> 6) << 2;            // 0,4,...,28
            float4 w;
            w.x = stage[(dl4 + 0) * 68 + p];
            w.y = stage[(dl4 + 1) * 68 + p];
            w.z = stage[(dl4 + 2) * 68 + p];
            w.w = stage[(dl4 + 3) * 68 + p];
            *(float4*)(z_s + p * ZS + dblk + dl4) = w;
        }
    }
    __syncthreads();

    // ---- zsq (proven rounding order) + esq into smem ----
    esq_s[tid] = g_esq[tid];
    if (tid < MT) {
        const float4* zr = (const float4*)(z_s + tid * ZS);
        float sx = 0.f, sy = 0.f, sz = 0.f, sw = 0.f;
#pragma unroll
        for (int i = 0; i < DDIM / 4; i++) {
            float4 v = zr[i];
            sx = __fadd_rn(sx, __fmul_rn(v.x, v.x));
            sy = __fadd_rn(sy, __fmul_rn(v.y, v.y));
            sz = __fadd_rn(sz, __fmul_rn(v.z, v.z));
            sw = __fadd_rn(sw, __fmul_rn(v.w, v.w));
        }
        zsq_s[tid] = __fadd_rn(__fadd_rn(sx, sy), __fadd_rn(sz, sw));
    }

    // ---- prefetch B block 0 via cp.async (2048 floats = 8KB) ----
    CP_ASYNC16(bbuf_s + tid * 16, (const void*)(e_frag + tid * 4));
    CP_COMMIT();
    __syncthreads();

    // per-slot best2: slot s = pixel-half (0: px0, 1: px0+8)
    float d1[2], d2[2];
    int   i1[2], i2[2];
    float acc[2][2][4];      // [j][ks-parity][frag] -> 4 independent chains/warp... x4 frag
#pragma unroll
    for (int s = 0; s < 2; s++) { d1[s] = 3.4e38f; d2[s] = 3.4e38f; i1[s] = 0; i2[s] = 0; }
#pragma unroll
    for (int j = 0; j < 2; j++)
#pragma unroll
        for (int p = 0; p < 2; p++)
#pragma unroll
            for (int r = 0; r < 4; r++) acc[j][p][r] = 0.f;

    for (int t = 0; t < 32; t++) {
        const int buf = t & 1;
        CP_WAIT0();
        __syncthreads();
        if (t + 1 < 32) {
            CP_ASYNC16(bbuf_s + ((buf ^ 1) * 2048 + tid * 4) * 4,
                       (const void*)(e_frag + (t + 1) * 2048 + tid * 4));
            CP_COMMIT();
        }

        const int kblk = (t & 3) * 64;
        const int mrow = wm * 16;
#pragma unroll
        for (int ks = 0; ks < 4; ks++) {           // k16 steps
            const int k0 = kblk + ks * 16 + 2 * tig;
            const float* zr0 = z_s + (mrow + g) * ZS + k0;
            const float* zr1 = z_s + (mrow + g + 8) * ZS + k0;
            float2 v00 = *(const float2*)(zr0);
            float2 v01 = *(const float2*)(zr0 + 8);
            float2 v10 = *(const float2*)(zr1);
            float2 v11 = *(const float2*)(zr1 + 8);

            uint32_t ah[4];
            ah[0] = f16pack(v00.y, v00.x);
            ah[1] = f16pack(v10.y, v10.x);
            ah[2] = f16pack(v01.y, v01.x);
            ah[3] = f16pack(v11.y, v11.x);

#pragma unroll
            for (int j = 0; j < 2; j++) {
                const int nt8 = wn * 2 + j;
                float2 bv = *(const float2*)(bbuf + (buf * 2048) +
                                             ((ks * 8 + nt8) * 32 + lane) * 2);
                mma_fp16(acc[j][ks & 1], ah,
                         __float_as_uint(bv.x), __float_as_uint(bv.y));
            }
        }

        // ---- end of nch: fold this K-chunk's dists into per-slot best2 ----
        if ((t & 3) == 3) {
            const int nch = t >> 2;
            const int px0 = wm * 16 + g;
            const float zq0 = zsq_s[px0];
            const float zq1 = zsq_s[px0 + 8];
#pragma unroll
            for (int j = 0; j < 2; j++) {
                const int c0 = nch * 64 + (wn * 2 + j) * 8 + 2 * tig;
                const float e0 = esq_s[c0], e1 = esq_s[c0 + 1];
                float cr[4];
#pragma unroll
                for (int q = 0; q < 4; q++) cr[q] = acc[j][0][q] + acc[j][1][q];
                float dd[4];
                dd[0] = (zq0 - 2.f * cr[0]) + e0;
                dd[1] = (zq0 - 2.f * cr[1]) + e1;
                dd[2] = (zq1 - 2.f * cr[2]) + e0;
                dd[3] = (zq1 - 2.f * cr[3]) + e1;
#pragma unroll
                for (int q = 0; q < 4; q++) {
                    const int s = q >> 1;
                    const int c = c0 + (q & 1);
                    const float d = dd[q];
                    if (d < d2[s]) {
                        if (d < d1[s]) { d2[s] = d1[s]; i2[s] = i1[s]; d1[s] = d; i1[s] = c; }
                        else           { d2[s] = d;     i2[s] = c; }
                    }
                    acc[j][0][q] = 0.f;
                    acc[j][1][q] = 0.f;
                }
            }
        }
    }

    // ---- dump 32 candidates per pixel (16 (wn,tig) slots x best2) into smem ----
    float* cand_d = bbuf;                   // [32][64]
    int*   cand_i = (int*)(bbuf + 2048);    // [32][64]
    __syncthreads();
#pragma unroll
    for (int s = 0; s < 2; s++) {
        const int px = wm * 16 + g + s * 8;          // 0..63
        const int sl = (wn * 4 + tig) * 2;           // 0..30
        cand_d[sl * 64 + px]       = d1[s];
        cand_i[sl * 64 + px]       = i1[s];
        cand_d[(sl + 1) * 64 + px] = d2[s];
        cand_i[(sl + 1) * 64 + px] = i2[s];
    }
    __syncthreads();

    // ---- exact rescore of candidates within EPS of mma-min (R4-proven order) ----
    if (tid < MT) {
        float mn = 3.4e38f;
#pragma unroll
        for (int s = 0; s < 32; s++) {
            float ad = cand_d[s * 64 + tid];
            if (ad < mn) mn = ad;
        }
        const float zq = zsq_s[tid];
        const float* zr = z_s + tid * ZS;
        float bestd = 3.4e38f;
        int   besti = 1 << 30;
#pragma unroll 1
        for (int s = 0; s < 32; s++) {
            float ad = cand_d[s * 64 + tid];
            if (ad < mn + EPS) {
                int c = cand_i[s * 64 + tid];
                const float* er = cb + (size_t)c * DDIM;
                float a = 0.f;
#pragma unroll 8
                for (int d = 0; d < DDIM; d++) a = fmaf(zr[d], __ldg(er + d), a);
                float dist = __fadd_rn(__fadd_rn(zq, -2.f * a), esq_s[c]);
                if (dist < bestd || (dist == bestd && c < besti)) { bestd = dist; besti = c; }
            }
        }
        out[pix_base + tid] = (float)besti;
    }
}

extern "C" void kernel_launch(void* const* d_in, const int* in_sizes, int n_in,
                              void* d_out, int out_size) {
    const float* a0 = (const float*)d_in[0];
    const float* a1 = (const float*)d_in[1];
    const float* z  = (in_sizes[0] > in_sizes[1]) ? a0 : a1;
    const float* cb = (in_sizes[0] > in_sizes[1]) ? a1 : a0;
    float* out = (float*)d_out;

    cudaFuncSetAttribute(vq_mma_kernel,
                         cudaFuncAttributeMaxDynamicSharedMemorySize,
                         SMEM_FLOATS * 4);

    prep_kernel<<<KCODES, DDIM / 2>>>(cb);
    vq_mma_kernel<<<NPIX / MT, THREADS, SMEM_FLOATS * 4>>>(z, cb, out);
}

// round 15
// speedup vs baseline: 1.6071x; 1.6071x over previous
#include <cuda_runtime.h>
#include <cuda_fp16.h>
#include <cstdint>

#define NPIX 65536
#define DDIM 256
#define KCODES 512
#define MT 128
#define THREADS 512
// smem float offsets
#define AF_OFF   0         // afrag: 8 mtiles x 16 ks x 32 lanes x uint4 = 16384 floats
#define B_OFF    16384     // 2 x 8192-float B buffers (32KB each); stage overlays here
#define ZSQP_OFF 32768     // 4 x 128 partials
#define ZSQ_OFF  33280     // 128
#define ESQ_OFF  33408     // 512
#define CD_OFF   33920     // cand_d [16][128]
#define CI_OFF   35968     // cand_i [16][128]
#define SMEM_FLOATS 38016  // 152,064 bytes
#define EPS 2e-4f          // rescue window (fp16 filter dist err ~1.4e-5 rms)

__device__ float g_esq[KCODES];
// B fragments (fp16): [super(8)][ks(16)][nt8(8)][lane(32)][b0,b1] u32 = 256KB
__device__ __align__(16) unsigned int e_frag[65536];

static __device__ __forceinline__ uint32_t smem_u32(const void* p) {
    uint32_t a;
    asm("{ .reg .u64 t; cvta.to.shared.u64 t, %1; cvt.u32.u64 %0, t; }" : "=r"(a) : "l"(p));
    return a;
}
// pack two f32 -> f16x2; SECOND operand lands in lower 16 bits (k-even)
static __device__ __forceinline__ uint32_t f16pack(float hi, float lo) {
    uint32_t r;
    asm("cvt.rn.f16x2.f32 %0, %1, %2;" : "=r"(r) : "f"(hi), "f"(lo));
    return r;
}
static __device__ __forceinline__ void mma_fp16(float* c, const uint32_t* a,
                                                uint32_t b0, uint32_t b1) {
    asm volatile("mma.sync.aligned.m16n8k16.row.col.f32.f16.f16.f32 "
                 "{%0,%1,%2,%3}, {%4,%5,%6,%7}, {%8,%9}, {%0,%1,%2,%3};"
                 : "+f"(c[0]), "+f"(c[1]), "+f"(c[2]), "+f"(c[3])
                 : "r"(a[0]), "r"(a[1]), "r"(a[2]), "r"(a[3]), "r"(b0), "r"(b1));
}
#define CP_ASYNC16(saddr, gptr) \
    asm volatile("cp.async.ca.shared.global [%0], [%1], 16;" :: "r"(saddr), "l"(gptr))
#define CP_COMMIT()  asm volatile("cp.async.commit_group;" ::: "memory")
#define CP_WAIT0()   asm volatile("cp.async.wait_group 0;" ::: "memory")

// ---- prep: scatter codebook into fp16 B-fragment image + esq (exact reference order) ----
__global__ void prep_kernel(const float* __restrict__ cb) {
    __shared__ float part[4];
    const int n = blockIdx.x;
    const int t = threadIdx.x;
    const int d = t * 2;
    const int g = n & 7, nt8 = (n >> 3) & 7, sup = n >> 6;

    float v0 = cb[n * DDIM + d];
    float v1 = cb[n * DDIM + d + 1];
    uint32_t pk = f16pack(v1, v0);          // lower 16 = k-even
    int ks   = d >> 4;                      // 0..15
    int ko   = d & 15;
    int half = ko >> 3;
    int tig  = (ko >> 1) & 3;
    int lane = g * 4 + tig;
    e_frag[(((sup * 16 + ks) * 8 + nt8) * 32 + lane) * 2 + half] = pk;

    if (t < 4) {
        float s = 0.f;
        for (int i = 0; i < DDIM / 4; i++) {
            float x = cb[n * DDIM + i * 4 + t];
            s = __fadd_rn(s, __fmul_rn(x, x));
        }
        part[t] = s;
    }
    __syncthreads();
    if (t == 0)
        g_esq[n] = __fadd_rn(__fadd_rn(part[0], part[1]), __fadd_rn(part[2], part[3]));
}

__global__ __launch_bounds__(THREADS, 1)
void vq_mma_kernel(const float* __restrict__ z, const float* __restrict__ cb,
                   float* __restrict__ out) {
    extern __shared__ __align__(16) float smem[];
    float*     bbuf   = smem + B_OFF;
    uint32_t*  afrag  = (uint32_t*)(smem + AF_OFF);
    float*     zsqp   = smem + ZSQP_OFF;
    float*     zsq_s  = smem + ZSQ_OFF;
    float*     esq_s  = smem + ESQ_OFF;
    float*     cand_d = smem + CD_OFF;
    int*       cand_i = (int*)(smem + CI_OFF);
    const uint32_t bbuf_s = smem_u32(bbuf);

    const int tid  = threadIdx.x;
    const int warp = tid >> 5;
    const int lane = tid & 31;
    const int g    = lane >> 2;      // 0..7
    const int tig  = lane & 3;       // 0..3
    const int wm   = warp & 7;       // M-warp -> mtile wm (16 px)
    const int wn   = warp >> 3;      // N-warp -> nt8 {wn*4..wn*4+3}

    const int pix_base = blockIdx.x * MT;
    const float* zbase = z + (size_t)(pix_base >> 10) * (DDIM * 1024) + (pix_base & 1023);

    esq_s[tid] = g_esq[tid];

    // ---- prologue: per 32-d block, stage z then build afrag + zsq partials ----
    // stage overlays B area: [32 d][128 px] stride 132
    float* stage = bbuf;
    {
        const int p_z  = tid & 127;          // zsq pixel
        const int j_z  = tid >> 7;           // zsq mod-4 lane
        float s_z = 0.f;
        // afrag slot for this thread (fixed across db): lane/ksl/mtile
        const int ksl = (tid >> 5) & 1;      // local ks within 32-d block
        const int mti = tid >> 6;            // 0..7
        const int k0l = ksl * 16 + 2 * tig;  // local d of k-pair start
        const int r0  = mti * 16 + g;
        const int r1  = r0 + 8;

        for (int db = 0; db < 8; db++) {
            __syncthreads();
#pragma unroll
            for (int it = 0; it < 2; it++) {
                int linear = tid + THREADS * it;        // 0..1023 float4
                int dd = linear >> 5;                   // 0..31
                int p4 = (linear & 31) << 2;            // 0..124
                float4 v = *(const float4*)(zbase + (size_t)(db * 32 + dd) * 1024 + p4);
                *(float4*)(stage + dd * 132 + p4) = v;
            }
            __syncthreads();
            // afrag build: 512 slots, one per thread
            {
                float s00 = stage[(k0l)     * 132 + r0];
                float s01 = stage[(k0l + 1) * 132 + r0];
                float s10 = stage[(k0l)     * 132 + r1];
                float s11 = stage[(k0l + 1) * 132 + r1];
                float s02 = stage[(k0l + 8) * 132 + r0];
                float s03 = stage[(k0l + 9) * 132 + r0];
                float s12 = stage[(k0l + 8) * 132 + r1];
                float s13 = stage[(k0l + 9) * 132 + r1];
                uint4 a;
                a.x = f16pack(s01, s00);
                a.y = f16pack(s11, s10);
                a.z = f16pack(s03, s02);
                a.w = f16pack(s13, s12);
                const int ksg = db * 2 + ksl;           // global ks 0..15
                *(uint4*)(afrag + ((mti * 16 + ksg) * 32 + lane) * 4) = a;
            }
            // zsq partial: dims db*32 + j_z + 4i, ascending
#pragma unroll
            for (int i = 0; i < 8; i++) {
                float x = stage[(j_z + 4 * i) * 132 + p_z];
                s_z = __fadd_rn(s_z, __fmul_rn(x, x));
            }
        }
        __syncthreads();
        zsqp[j_z * 128 + p_z] = s_z;
    }
    __syncthreads();
    if (tid < MT)
        zsq_s[tid] = __fadd_rn(__fadd_rn(zsqp[tid], zsqp[128 + tid]),
                               __fadd_rn(zsqp[256 + tid], zsqp[384 + tid]));

    // ---- prefetch B super 0 (8192 u32 = 32KB) ----
    __syncthreads();   // stage fully consumed before overwriting B area
#pragma unroll
    for (int it = 0; it < 4; it++) {
        int fo = tid * 4 + it * 2048;   // u32 offset
        CP_ASYNC16(bbuf_s + fo * 4, (const void*)(e_frag + fo));
    }
    CP_COMMIT();

    // per-slot best2: slot s = pixel-half (0: px0, 1: px0+8)
    float d1[2], d2[2];
    int   i1[2], i2[2];
    float acc[4][4];
#pragma unroll
    for (int s = 0; s < 2; s++) { d1[s] = 3.4e38f; d2[s] = 3.4e38f; i1[s] = 0; i2[s] = 0; }
#pragma unroll
    for (int j = 0; j < 4; j++)
#pragma unroll
        for (int r = 0; r < 4; r++) acc[j][r] = 0.f;

    const uint32_t* afw = afrag + (wm * 16) * 32 * 4;   // this warp's mtile

    for (int s = 0; s < 8; s++) {       // 8 supers x 64 codes
        const int buf = s & 1;
        CP_WAIT0();
        __syncthreads();
        if (s + 1 < 8) {
#pragma unroll
            for (int it = 0; it < 4; it++) {
                int fo = tid * 4 + it * 2048;
                CP_ASYNC16(bbuf_s + ((buf ^ 1) * 8192 + fo) * 4,
                           (const void*)(e_frag + (s + 1) * 8192 + fo));
            }
            CP_COMMIT();
        }

        const float* bb = bbuf + buf * 8192;
#pragma unroll
        for (int ks = 0; ks < 16; ks++) {
            uint4 av = *(const uint4*)(afw + (ks * 32 + lane) * 4);
            uint32_t a4[4] = {av.x, av.y, av.z, av.w};
#pragma unroll
            for (int j = 0; j < 4; j++) {
                const int nt8 = wn * 4 + j;
                float2 bv = *(const float2*)(bb + ((ks * 8 + nt8) * 32 + lane) * 2);
                mma_fp16(acc[j], a4, __float_as_uint(bv.x), __float_as_uint(bv.y));
            }
        }

        // ---- fold this super's 64 codes into per-slot best2 ----
        {
            const int px0 = wm * 16 + g;
            const float zq0 = zsq_s[px0];
            const float zq1 = zsq_s[px0 + 8];
#pragma unroll
            for (int j = 0; j < 4; j++) {
                const int c0 = s * 64 + (wn * 4 + j) * 8 + 2 * tig;
                const float e0 = esq_s[c0], e1 = esq_s[c0 + 1];
                float dd[4];
                dd[0] = (zq0 - 2.f * acc[j][0]) + e0;
                dd[1] = (zq0 - 2.f * acc[j][1]) + e1;
                dd[2] = (zq1 - 2.f * acc[j][2]) + e0;
                dd[3] = (zq1 - 2.f * acc[j][3]) + e1;
#pragma unroll
                for (int q = 0; q < 4; q++) {
                    const int sl = q >> 1;
                    const int c = c0 + (q & 1);
                    const float d = dd[q];
                    if (d < d2[sl]) {
                        if (d < d1[sl]) { d2[sl] = d1[sl]; i2[sl] = i1[sl]; d1[sl] = d; i1[sl] = c; }
                        else            { d2[sl] = d;      i2[sl] = c; }
                    }
                    acc[j][q] = 0.f;
                }
            }
        }
    }

    // ---- dump 16 candidates per pixel (8 (wn,tig) slots x best2) ----
    __syncthreads();
#pragma unroll
    for (int s = 0; s < 2; s++) {
        const int px = wm * 16 + g + s * 8;
        const int sl = (wn * 4 + tig) * 2;
        cand_d[sl * 128 + px]       = d1[s];
        cand_i[sl * 128 + px]       = i1[s];
        cand_d[(sl + 1) * 128 + px] = d2[s];
        cand_i[(sl + 1) * 128 + px] = i2[s];
    }
    __syncthreads();

    // ---- exact rescore within EPS of mma-min (R4-proven ascending-d fmaf order) ----
    if (tid < MT) {
        float mn = 3.4e38f;
#pragma unroll
        for (int s = 0; s < 16; s++) {
            float ad = cand_d[s * 128 + tid];
            if (ad < mn) mn = ad;
        }
        const float zq = zsq_s[tid];
        const float* zg = zbase + tid;      // z[px=tid][d] at stride 1024 (L2-resident)
        float bestd = 3.4e38f;
        int   besti = 1 << 30;
#pragma unroll 1
        for (int s = 0; s < 16; s++) {
            float ad = cand_d[s * 128 + tid];
            if (ad < mn + EPS) {
                int c = cand_i[s * 128 + tid];
                const float* er = cb + (size_t)c * DDIM;
                float a = 0.f;
#pragma unroll 8
                for (int d = 0; d < DDIM; d++)
                    a = fmaf(zg[(size_t)d << 10], __ldg(er + d), a);
                float dist = __fadd_rn(__fadd_rn(zq, -2.f * a), esq_s[c]);
                if (dist < bestd || (dist == bestd && c < besti)) { bestd = dist; besti = c; }
            }
        }
        out[pix_base + tid] = (float)besti;
    }
}

extern "C" void kernel_launch(void* const* d_in, const int* in_sizes, int n_in,
                              void* d_out, int out_size) {
    const float* a0 = (const float*)d_in[0];
    const float* a1 = (const float*)d_in[1];
    const float* z  = (in_sizes[0] > in_sizes[1]) ? a0 : a1;
    const float* cb = (in_sizes[0] > in_sizes[1]) ? a1 : a0;
    float* out = (float*)d_out;

    cudaFuncSetAttribute(vq_mma_kernel,
                         cudaFuncAttributeMaxDynamicSharedMemorySize,
                         SMEM_FLOATS * 4);

    prep_kernel<<<KCODES, DDIM / 2>>>(cb);
    vq_mma_kernel<<<NPIX / MT, THREADS, SMEM_FLOATS * 4>>>(z, cb, out);
}

// round 16
// speedup vs baseline: 2.1565x; 1.3418x over previous
#include <cuda_runtime.h>
#include <cuda_fp16.h>
#include <cstdint>

#define NPIX 65536
#define DDIM 256
#define KCODES 512
#define MT 128
#define THREADS 512
// smem float offsets
#define AF_OFF   0         // afrag: 8 mtiles x 16 ks x 32 lanes x uint4 = 16384 floats
#define B_OFF    16384     // 2 x 4096-float B buffers (16KB each); stage + cands overlay
#define ZSQP_OFF 24576     // 4 x 128 partials
#define ZSQ_OFF  25088     // 128
#define ESQ_OFF  25216     // 512
#define CD_OFF   16384     // cand_d [16][128] overlays B (post-mainloop)
#define CI_OFF   18432     // cand_i [16][128]
#define SMEM_FLOATS 25728  // 102,912 bytes -> 2 CTAs/SM
#define EPS 2e-4f          // rescue window (fp16 filter dist err ~1.4e-5 rms)

__device__ float g_esq[KCODES];
// B fragments (fp16): [sup(16)][ks(16)][nt4(4)][lane(32)][b0,b1] u32 = 256KB
__device__ __align__(16) unsigned int e_frag[65536];

static __device__ __forceinline__ uint32_t smem_u32(const void* p) {
    uint32_t a;
    asm("{ .reg .u64 t; cvta.to.shared.u64 t, %1; cvt.u32.u64 %0, t; }" : "=r"(a) : "l"(p));
    return a;
}
// pack two f32 -> f16x2; SECOND operand lands in lower 16 bits (k-even)
static __device__ __forceinline__ uint32_t f16pack(float hi, float lo) {
    uint32_t r;
    asm("cvt.rn.f16x2.f32 %0, %1, %2;" : "=r"(r) : "f"(hi), "f"(lo));
    return r;
}
static __device__ __forceinline__ void mma_fp16(float* c, const uint32_t* a,
                                                uint32_t b0, uint32_t b1) {
    asm volatile("mma.sync.aligned.m16n8k16.row.col.f32.f16.f16.f32 "
                 "{%0,%1,%2,%3}, {%4,%5,%6,%7}, {%8,%9}, {%0,%1,%2,%3};"
                 : "+f"(c[0]), "+f"(c[1]), "+f"(c[2]), "+f"(c[3])
                 : "r"(a[0]), "r"(a[1]), "r"(a[2]), "r"(a[3]), "r"(b0), "r"(b1));
}
#define CP_ASYNC16(saddr, gptr) \
    asm volatile("cp.async.ca.shared.global [%0], [%1], 16;" :: "r"(saddr), "l"(gptr))
#define CP_COMMIT()  asm volatile("cp.async.commit_group;" ::: "memory")
#define CP_WAIT0()   asm volatile("cp.async.wait_group 0;" ::: "memory")

// ---- prep: scatter codebook into fp16 B-fragment image + esq (exact reference order) ----
__global__ void prep_kernel(const float* __restrict__ cb) {
    __shared__ float part[4];
    const int n = blockIdx.x;
    const int t = threadIdx.x;
    const int d = t * 2;
    const int g = n & 7, nt4 = (n >> 3) & 3, sup = n >> 5;

    float v0 = cb[n * DDIM + d];
    float v1 = cb[n * DDIM + d + 1];
    uint32_t pk = f16pack(v1, v0);          // lower 16 = k-even
    int ks   = d >> 4;                      // 0..15
    int ko   = d & 15;
    int half = ko >> 3;
    int tig  = (ko >> 1) & 3;
    int lane = g * 4 + tig;
    e_frag[((((sup * 16 + ks) * 4 + nt4) * 32) + lane) * 2 + half] = pk;

    if (t < 4) {
        float s = 0.f;
        for (int i = 0; i < DDIM / 4; i++) {
            float x = cb[n * DDIM + i * 4 + t];
            s = __fadd_rn(s, __fmul_rn(x, x));
        }
        part[t] = s;
    }
    __syncthreads();
    if (t == 0)
        g_esq[n] = __fadd_rn(__fadd_rn(part[0], part[1]), __fadd_rn(part[2], part[3]));
}

__global__ __launch_bounds__(THREADS, 2)
void vq_mma_kernel(const float* __restrict__ z, const float* __restrict__ cb,
                   float* __restrict__ out) {
    extern __shared__ __align__(16) float smem[];
    float*     bbuf   = smem + B_OFF;
    uint32_t*  afrag  = (uint32_t*)(smem + AF_OFF);
    float*     zsqp   = smem + ZSQP_OFF;
    float*     zsq_s  = smem + ZSQ_OFF;
    float*     esq_s  = smem + ESQ_OFF;
    float*     cand_d = smem + CD_OFF;
    int*       cand_i = (int*)(smem + CI_OFF);
    const uint32_t bbuf_s = smem_u32(bbuf);

    const int tid  = threadIdx.x;
    const int warp = tid >> 5;
    const int lane = tid & 31;
    const int g    = lane >> 2;      // 0..7
    const int tig  = lane & 3;       // 0..3
    const int wm   = warp & 7;       // M-warp -> mtile wm (16 px)
    const int wn   = warp >> 3;      // N-warp -> nt4 {wn*2, wn*2+1}

    const int pix_base = blockIdx.x * MT;
    const float* zbase = z + (size_t)(pix_base >> 10) * (DDIM * 1024) + (pix_base & 1023);

    esq_s[tid] = g_esq[tid];

    // ---- prologue: per 32-d block, stage z then build afrag + zsq partials ----
    // stage overlays B area: [32 d][128 px] stride 132 (4224 <= 8192 floats)
    float* stage = bbuf;
    {
        const int p_z  = tid & 127;          // zsq pixel
        const int j_z  = tid >> 7;           // zsq mod-4 lane
        float s_z = 0.f;
        const int ksl = (tid >> 5) & 1;      // local ks within 32-d block
        const int mti = tid >> 6;            // 0..7
        const int k0l = ksl * 16 + 2 * tig;  // local d of k-pair start
        const int r0  = mti * 16 + g;
        const int r1  = r0 + 8;

        for (int db = 0; db < 8; db++) {
            __syncthreads();
#pragma unroll
            for (int it = 0; it < 2; it++) {
                int linear = tid + THREADS * it;        // 0..1023 float4
                int dd = linear >> 5;                   // 0..31
                int p4 = (linear & 31) << 2;            // 0..124
                float4 v = *(const float4*)(zbase + (size_t)(db * 32 + dd) * 1024 + p4);
                *(float4*)(stage + dd * 132 + p4) = v;
            }
            __syncthreads();
            {
                float s00 = stage[(k0l)     * 132 + r0];
                float s01 = stage[(k0l + 1) * 132 + r0];
                float s10 = stage[(k0l)     * 132 + r1];
                float s11 = stage[(k0l + 1) * 132 + r1];
                float s02 = stage[(k0l + 8) * 132 + r0];
                float s03 = stage[(k0l + 9) * 132 + r0];
                float s12 = stage[(k0l + 8) * 132 + r1];
                float s13 = stage[(k0l + 9) * 132 + r1];
                uint4 a;
                a.x = f16pack(s01, s00);
                a.y = f16pack(s11, s10);
                a.z = f16pack(s03, s02);
                a.w = f16pack(s13, s12);
                const int ksg = db * 2 + ksl;           // global ks 0..15
                *(uint4*)(afrag + ((mti * 16 + ksg) * 32 + lane) * 4) = a;
            }
#pragma unroll
            for (int i = 0; i < 8; i++) {
                float x = stage[(j_z + 4 * i) * 132 + p_z];
                s_z = __fadd_rn(s_z, __fmul_rn(x, x));
            }
        }
        __syncthreads();
        zsqp[j_z * 128 + p_z] = s_z;
    }
    __syncthreads();
    if (tid < MT)
        zsq_s[tid] = __fadd_rn(__fadd_rn(zsqp[tid], zsqp[128 + tid]),
                               __fadd_rn(zsqp[256 + tid], zsqp[384 + tid]));

    // ---- prefetch B super 0 (4096 u32 = 16KB) ----
    __syncthreads();   // stage fully consumed before overwriting B area
#pragma unroll
    for (int it = 0; it < 2; it++) {
        int fo = tid * 4 + it * 2048;   // u32 offset
        CP_ASYNC16(bbuf_s + fo * 4, (const void*)(e_frag + fo));
    }
    CP_COMMIT();

    // per-slot best2: slot s = pixel-half (0: px0, 1: px0+8)
    float d1[2], d2[2];
    int   i1[2], i2[2];
    float acc[2][4];
#pragma unroll
    for (int s = 0; s < 2; s++) { d1[s] = 3.4e38f; d2[s] = 3.4e38f; i1[s] = 0; i2[s] = 0; }
#pragma unroll
    for (int j = 0; j < 2; j++)
#pragma unroll
        for (int r = 0; r < 4; r++) acc[j][r] = 0.f;

    const uint32_t* afw = afrag + (wm * 16) * 32 * 4;   // this warp's mtile

    for (int s = 0; s < 16; s++) {       // 16 supers x 32 codes
        const int buf = s & 1;
        CP_WAIT0();
        __syncthreads();
        if (s + 1 < 16) {
#pragma unroll
            for (int it = 0; it < 2; it++) {
                int fo = tid * 4 + it * 2048;
                CP_ASYNC16(bbuf_s + ((buf ^ 1) * 4096 + fo) * 4,
                           (const void*)(e_frag + (s + 1) * 4096 + fo));
            }
            CP_COMMIT();
        }

        const float* bb = bbuf + buf * 4096;
#pragma unroll
        for (int ks = 0; ks < 16; ks++) {
            uint4 av = *(const uint4*)(afw + (ks * 32 + lane) * 4);
            uint32_t a4[4] = {av.x, av.y, av.z, av.w};
#pragma unroll
            for (int j = 0; j < 2; j++) {
                const int nt4 = wn * 2 + j;
                float2 bv = *(const float2*)(bb + ((ks * 4 + nt4) * 32 + lane) * 2);
                mma_fp16(acc[j], a4, __float_as_uint(bv.x), __float_as_uint(bv.y));
            }
        }

        // ---- fold this super's 32 codes into per-slot best2 ----
        {
            const int px0 = wm * 16 + g;
            const float zq0 = zsq_s[px0];
            const float zq1 = zsq_s[px0 + 8];
#pragma unroll
            for (int j = 0; j < 2; j++) {
                const int c0 = s * 32 + (wn * 2 + j) * 8 + 2 * tig;
                const float e0 = esq_s[c0], e1 = esq_s[c0 + 1];
                float dd[4];
                dd[0] = (zq0 - 2.f * acc[j][0]) + e0;
                dd[1] = (zq0 - 2.f * acc[j][1]) + e1;
                dd[2] = (zq1 - 2.f * acc[j][2]) + e0;
                dd[3] = (zq1 - 2.f * acc[j][3]) + e1;
#pragma unroll
                for (int q = 0; q < 4; q++) {
                    const int sl = q >> 1;
                    const int c = c0 + (q & 1);
                    const float d = dd[q];
                    if (d < d2[sl]) {
                        if (d < d1[sl]) { d2[sl] = d1[sl]; i2[sl] = i1[sl]; d1[sl] = d; i1[sl] = c; }
                        else            { d2[sl] = d;      i2[sl] = c; }
                    }
                    acc[j][q] = 0.f;
                }
            }
        }
    }

    // ---- dump 16 candidates per pixel (8 (wn,tig) slots x best2) ----
    __syncthreads();
#pragma unroll
    for (int s = 0; s < 2; s++) {
        const int px = wm * 16 + g + s * 8;
        const int sl = (wn * 4 + tig) * 2;
        cand_d[sl * 128 + px]       = d1[s];
        cand_i[sl * 128 + px]       = i1[s];
        cand_d[(sl + 1) * 128 + px] = d2[s];
        cand_i[(sl + 1) * 128 + px] = i2[s];
    }
    __syncthreads();

    // ---- exact rescore within EPS of mma-min (R4-proven ascending-d fmaf order) ----
    if (tid < MT) {
        float mn = 3.4e38f;
#pragma unroll
        for (int s = 0; s < 16; s++) {
            float ad = cand_d[s * 128 + tid];
            if (ad < mn) mn = ad;
        }
        const float zq = zsq_s[tid];
        const float* zg = zbase + tid;      // z[px=tid][d] at stride 1024 (L2-resident)
        float bestd = 3.4e38f;
        int   besti = 1 << 30;
#pragma unroll 1
        for (int s = 0; s < 16; s++) {
            float ad = cand_d[s * 128 + tid];
            if (ad < mn + EPS) {
                int c = cand_i[s * 128 + tid];
                const float* er = cb + (size_t)c * DDIM;
                float a = 0.f;
#pragma unroll 8
                for (int d = 0; d < DDIM; d++)
                    a = fmaf(zg[(size_t)d << 10], __ldg(er + d), a);
                float dist = __fadd_rn(__fadd_rn(zq, -2.f * a), esq_s[c]);
                if (dist < bestd || (dist == bestd && c < besti)) { bestd = dist; besti = c; }
            }
        }
        out[pix_base + tid] = (float)besti;
    }
}

extern "C" void kernel_launch(void* const* d_in, const int* in_sizes, int n_in,
                              void* d_out, int out_size) {
    const float* a0 = (const float*)d_in[0];
    const float* a1 = (const float*)d_in[1];
    const float* z  = (in_sizes[0] > in_sizes[1]) ? a0 : a1;
    const float* cb = (in_sizes[0] > in_sizes[1]) ? a1 : a0;
    float* out = (float*)d_out;

    cudaFuncSetAttribute(vq_mma_kernel,
                         cudaFuncAttributeMaxDynamicSharedMemorySize,
                         SMEM_FLOATS * 4);

    prep_kernel<<<KCODES, DDIM / 2>>>(cb);
    vq_mma_kernel<<<NPIX / MT, THREADS, SMEM_FLOATS * 4>>>(z, cb, out);
}